// round 1
// baseline (speedup 1.0000x reference)
#include <cuda_runtime.h>
#include <float.h>

#define BB  8
#define NN  2048
#define KNN 20

// ---------------- scratch (device globals; no allocations) ----------------
__device__ float g_d2[(size_t)BB * NN * NN];      // 134 MB pairwise distances
__device__ float g_xx[BB * NN];                   // squared norms
__device__ int   g_idx[BB * NN * KNN];            // knn indices
__device__ float g_y[(size_t)BB * NN * 256];      // Y = X * W[:, :C]^T
__device__ float g_c[(size_t)BB * NN * 256];      // C = X * W[:, C:]^T + b
__device__ float g_hcat[(size_t)BB * NN * 512];   // concatenated layer outputs
__device__ float g_tmp[(size_t)BB * NN * 1024];   // final linear pre-pool

// ---------------- squared norms ----------------
__global__ void xx_kernel(const float* __restrict__ X, int ldx, int C,
                          float* __restrict__ xx) {
    int i = blockIdx.x * blockDim.x + threadIdx.x;
    if (i >= BB * NN) return;
    const float* p = X + (size_t)i * ldx;
    float s = 0.f;
    for (int c = 0; c < C; ++c) { float v = p[c]; s += v * v; }
    xx[i] = s;
}

// ---------------- pairwise d2 = |xi|^2 - 2 xi.xj + |xj|^2 (64x64 tile, 4x4 micro) ----------------
__global__ void pairwise64(const float* __restrict__ X, int ldx, int C,
                           const float* __restrict__ xx, float* __restrict__ d2) {
    __shared__ float As[64][33];
    __shared__ float Bs[64][33];
    int b  = blockIdx.z;
    int r0 = blockIdx.y * 64, c0 = blockIdx.x * 64;
    int tx = threadIdx.x, ty = threadIdx.y;
    int tid = ty * 16 + tx;
    const float* Xb  = X + (size_t)b * NN * ldx;
    const float* xxb = xx + b * NN;
    float acc[4][4] = {};
    for (int k0 = 0; k0 < C; k0 += 32) {
#pragma unroll
        for (int i = 0; i < 8; ++i) {
            int e = tid + i * 256;
            int row = e >> 5, kc = e & 31;
            int kk = k0 + kc;
            As[row][kc] = (kk < C) ? Xb[(size_t)(r0 + row) * ldx + kk] : 0.f;
            Bs[row][kc] = (kk < C) ? Xb[(size_t)(c0 + row) * ldx + kk] : 0.f;
        }
        __syncthreads();
#pragma unroll
        for (int k = 0; k < 32; ++k) {
            float a[4], bb[4];
#pragma unroll
            for (int i = 0; i < 4; ++i) { a[i] = As[ty + 16 * i][k]; bb[i] = Bs[tx + 16 * i][k]; }
#pragma unroll
            for (int i = 0; i < 4; ++i)
#pragma unroll
                for (int j = 0; j < 4; ++j) acc[i][j] += a[i] * bb[j];
        }
        __syncthreads();
    }
#pragma unroll
    for (int i = 0; i < 4; ++i) {
        int r = r0 + ty + 16 * i;
        float xr = xxb[r];
#pragma unroll
        for (int j = 0; j < 4; ++j) {
            int cc = c0 + tx + 16 * j;
            d2[((size_t)b * NN + r) * NN + cc] = xr - 2.f * acc[i][j] + xxb[cc];
        }
    }
}

// ---------------- top-K smallest per row (repeated argmin, tie -> lowest idx) ----------------
__global__ void topk_kernel(const float* __restrict__ d2, int* __restrict__ idx) {
    __shared__ float sv[NN];
    __shared__ float rv[128];
    __shared__ int   ri[128];
    int b = blockIdx.y, n = blockIdx.x;
    int t = threadIdx.x;
    const float* row = d2 + ((size_t)b * NN + n) * NN;
    for (int i = t; i < NN; i += 128) sv[i] = row[i];
    __syncthreads();
    for (int k = 0; k < KNN; ++k) {
        float bv = FLT_MAX; int bi = NN;
        for (int i = t; i < NN; i += 128) {
            float v = sv[i];
            if (v < bv) { bv = v; bi = i; }   // ascending scan keeps lowest tie index
        }
        rv[t] = bv; ri[t] = bi;
        __syncthreads();
        for (int s = 64; s > 0; s >>= 1) {
            if (t < s) {
                float v2 = rv[t + s]; int i2 = ri[t + s];
                if (v2 < rv[t] || (v2 == rv[t] && i2 < ri[t])) { rv[t] = v2; ri[t] = i2; }
            }
            __syncthreads();
        }
        if (t == 0) { idx[((size_t)b * NN + n) * KNN + k] = ri[0]; sv[ri[0]] = FLT_MAX; }
        __syncthreads();
    }
}

// ---------------- generic SGEMM: out[m,o] = sum_k X[m,k] * W[o, woff+k] (+bias, leaky) ----------------
__global__ void gemm64(const float* __restrict__ X, int ldx,
                       const float* __restrict__ W, int wld, int woff,
                       const float* __restrict__ bias,
                       float* __restrict__ out, int ldo,
                       int K, int act) {
    __shared__ float Xs[64][33];
    __shared__ float Ws[64][33];
    int m0 = blockIdx.y * 64, o0 = blockIdx.x * 64;
    int tx = threadIdx.x, ty = threadIdx.y;
    int tid = ty * 16 + tx;
    float acc[4][4] = {};
    for (int k0 = 0; k0 < K; k0 += 32) {
#pragma unroll
        for (int i = 0; i < 8; ++i) {
            int e = tid + i * 256;
            int row = e >> 5, kc = e & 31;
            int kk = k0 + kc;
            Xs[row][kc] = (kk < K) ? X[(size_t)(m0 + row) * ldx + kk] : 0.f;
            Ws[row][kc] = (kk < K) ? W[(size_t)(o0 + row) * wld + woff + kk] : 0.f;
        }
        __syncthreads();
#pragma unroll
        for (int k = 0; k < 32; ++k) {
            float a[4], bb[4];
#pragma unroll
            for (int i = 0; i < 4; ++i) { a[i] = Xs[ty + 16 * i][k]; bb[i] = Ws[tx + 16 * i][k]; }
#pragma unroll
            for (int i = 0; i < 4; ++i)
#pragma unroll
                for (int j = 0; j < 4; ++j) acc[i][j] += a[i] * bb[j];
        }
        __syncthreads();
    }
#pragma unroll
    for (int i = 0; i < 4; ++i) {
        int m = m0 + ty + 16 * i;
#pragma unroll
        for (int j = 0; j < 4; ++j) {
            int o = o0 + tx + 16 * j;
            float v = acc[i][j];
            if (bias) v += bias[o];
            if (act)  v = v > 0.f ? v : 0.2f * v;
            out[(size_t)m * ldo + o] = v;
        }
    }
}

// ---------------- edge epilogue: h[n,o] = max_k leaky(Y[j_k,o] - Y[n,o] + C[n,o]) ----------------
__global__ void edgemax(const float* __restrict__ y, const float* __restrict__ c,
                        const int* __restrict__ idx, float* __restrict__ out,
                        int O, int ldo) {
    __shared__ int sid[KNN];
    int b = blockIdx.y, n = blockIdx.x;
    int t = threadIdx.x;  // blockDim.x == O
    if (t < KNN) sid[t] = idx[((size_t)b * NN + n) * KNN + t];
    __syncthreads();
    size_t mbase = (size_t)b * NN;
    float yc = y[(mbase + n) * O + t];
    float cc = c[(mbase + n) * O + t];
    float m = -FLT_MAX;
#pragma unroll
    for (int k = 0; k < KNN; ++k) {
        float v = y[(mbase + sid[k]) * O + t] - yc + cc;
        v = v > 0.f ? v : 0.2f * v;
        m = fmaxf(m, v);
    }
    out[(mbase + n) * ldo + t] = m;
}

// ---------------- global max pool over N ----------------
__global__ void maxpool(const float* __restrict__ tmp, float* __restrict__ out) {
    int b = blockIdx.y;
    int f = blockIdx.x * blockDim.x + threadIdx.x;  // 0..1023
    const float* p = tmp + (size_t)b * NN * 1024 + f;
    float m = -FLT_MAX;
    for (int n = 0; n < NN; ++n) m = fmaxf(m, p[(size_t)n * 1024]);
    out[b * 1024 + f] = m;
}

// ---------------- launch ----------------
extern "C" void kernel_launch(void* const* d_in, const int* in_sizes, int n_in,
                              void* d_out, int out_size) {
    const float* x     = (const float*)d_in[0];
    const float* Wl[4] = {(const float*)d_in[1], (const float*)d_in[3],
                          (const float*)d_in[5], (const float*)d_in[7]};
    const float* bl[4] = {(const float*)d_in[2], (const float*)d_in[4],
                          (const float*)d_in[6], (const float*)d_in[8]};
    const float* Wf = (const float*)d_in[9];
    const float* bf = (const float*)d_in[10];
    float* out = (float*)d_out;

    float *p_d2, *p_xx, *p_y, *p_c, *p_hcat, *p_tmp;
    int* p_idx;
    cudaGetSymbolAddress((void**)&p_d2,   g_d2);
    cudaGetSymbolAddress((void**)&p_xx,   g_xx);
    cudaGetSymbolAddress((void**)&p_idx,  g_idx);
    cudaGetSymbolAddress((void**)&p_y,    g_y);
    cudaGetSymbolAddress((void**)&p_c,    g_c);
    cudaGetSymbolAddress((void**)&p_hcat, g_hcat);
    cudaGetSymbolAddress((void**)&p_tmp,  g_tmp);

    const int Cs[4]  = {3, 64, 64, 128};
    const int Os[4]  = {64, 64, 128, 256};
    const int off[4] = {0, 64, 128, 256};

    const float* Xin = x;
    int ldx = 3;
    for (int l = 0; l < 4; ++l) {
        int C = Cs[l], O = Os[l];
        xx_kernel<<<(BB * NN + 255) / 256, 256>>>(Xin, ldx, C, p_xx);
        pairwise64<<<dim3(NN / 64, NN / 64, BB), dim3(16, 16)>>>(Xin, ldx, C, p_xx, p_d2);
        topk_kernel<<<dim3(NN, BB), 128>>>(p_d2, p_idx);
        gemm64<<<dim3(O / 64, (BB * NN) / 64), dim3(16, 16)>>>(
            Xin, ldx, Wl[l], 2 * C, 0, nullptr, p_y, O, C, 0);
        gemm64<<<dim3(O / 64, (BB * NN) / 64), dim3(16, 16)>>>(
            Xin, ldx, Wl[l], 2 * C, C, bl[l], p_c, O, C, 0);
        edgemax<<<dim3(NN, BB), O>>>(p_y, p_c, p_idx, p_hcat + off[l], O, 512);
        Xin = p_hcat + off[l];
        ldx = 512;
    }
    // final 512 -> 1024 linear + leaky, then max over N
    gemm64<<<dim3(1024 / 64, (BB * NN) / 64), dim3(16, 16)>>>(
        p_hcat, 512, Wf, 512, 0, bf, p_tmp, 1024, 512, 1);
    maxpool<<<dim3(1024 / 256, BB), 256>>>(p_tmp, out);
}

// round 2
// speedup vs baseline: 1.1953x; 1.1953x over previous
#include <cuda_runtime.h>
#include <float.h>
#include <math.h>

#define BB  8
#define NN  2048
#define KNN 20

// ---------------- scratch (device globals; no allocations) ----------------
__device__ float g_d2[(size_t)BB * NN * NN];      // 134 MB pairwise distances
__device__ float g_xx[BB * NN];                   // squared norms
__device__ int   g_idx[BB * NN * KNN];            // knn indices
__device__ float g_y[(size_t)BB * NN * 256];      // Y = X * W[:, :C]^T
__device__ float g_c[(size_t)BB * NN * 256];      // C = X * W[:, C:]^T + b
__device__ float g_hcat[(size_t)BB * NN * 512];   // concatenated layer outputs
__device__ float g_tmp[(size_t)BB * NN * 1024];   // final linear pre-pool

// ---------------- squared norms ----------------
__global__ void xx_kernel(const float* __restrict__ X, int ldx, int C,
                          float* __restrict__ xx) {
    int i = blockIdx.x * blockDim.x + threadIdx.x;
    if (i >= BB * NN) return;
    const float* p = X + (size_t)i * ldx;
    float s = 0.f;
    for (int c = 0; c < C; ++c) { float v = p[c]; s += v * v; }
    xx[i] = s;
}

// ---------------- pairwise d2, symmetric: only lower-tri 128-tiles, mirror store ----
__global__ void pairwise128(const float* __restrict__ X, int ldx, int C,
                            const float* __restrict__ xx, float* __restrict__ d2) {
    __shared__ float As[16][132];
    __shared__ float Bs[16][132];
    int b = blockIdx.y;
    int t = blockIdx.x;
    int bi = (int)((sqrtf(8.f * t + 1.f) - 1.f) * 0.5f);
    while ((bi + 1) * (bi + 2) / 2 <= t) ++bi;
    while (bi * (bi + 1) / 2 > t) --bi;
    int bj = t - bi * (bi + 1) / 2;
    int r0 = bi * 128, c0 = bj * 128;

    const float* Xb  = X + (size_t)b * NN * ldx;
    const float* xxb = xx + b * NN;
    float* out = d2 + (size_t)b * NN * NN;

    int tx = threadIdx.x & 15, ty = threadIdx.x >> 4;
    float acc[8][8] = {};

    for (int k0 = 0; k0 < C; k0 += 16) {
#pragma unroll
        for (int i = 0; i < 8; ++i) {
            int e = threadIdx.x + 256 * i;
            int m = e >> 4, kk = e & 15;
            int kg = k0 + kk;
            As[kk][m] = (kg < C) ? Xb[(size_t)(r0 + m) * ldx + kg] : 0.f;
            Bs[kk][m] = (kg < C) ? Xb[(size_t)(c0 + m) * ldx + kg] : 0.f;
        }
        __syncthreads();
#pragma unroll
        for (int k = 0; k < 16; ++k) {
            float a[8], bb[8];
            *(float4*)&a[0]  = *(const float4*)&As[k][ty * 8];
            *(float4*)&a[4]  = *(const float4*)&As[k][ty * 8 + 4];
            *(float4*)&bb[0] = *(const float4*)&Bs[k][tx * 8];
            *(float4*)&bb[4] = *(const float4*)&Bs[k][tx * 8 + 4];
#pragma unroll
            for (int i = 0; i < 8; ++i)
#pragma unroll
                for (int j = 0; j < 8; ++j) acc[i][j] += a[i] * bb[j];
        }
        __syncthreads();
    }

    float xr[8], xc[8], v[8][8];
#pragma unroll
    for (int i = 0; i < 8; ++i) xr[i] = xxb[r0 + ty * 8 + i];
#pragma unroll
    for (int j = 0; j < 8; ++j) xc[j] = xxb[c0 + tx * 8 + j];
#pragma unroll
    for (int i = 0; i < 8; ++i)
#pragma unroll
        for (int j = 0; j < 8; ++j) v[i][j] = xr[i] - 2.f * acc[i][j] + xc[j];

    // normal tile store (rows r, cols c) — contiguous over j
#pragma unroll
    for (int i = 0; i < 8; ++i) {
        int r = r0 + ty * 8 + i;
        float* p = out + (size_t)r * NN + c0 + tx * 8;
        *(float4*)p       = *(float4*)&v[i][0];
        *(float4*)(p + 4) = *(float4*)&v[i][4];
    }
    // mirrored store (rows c, cols r) — contiguous over i
    if (bi != bj) {
#pragma unroll
        for (int j = 0; j < 8; ++j) {
            int c = c0 + tx * 8 + j;
            float4 lo = make_float4(v[0][j], v[1][j], v[2][j], v[3][j]);
            float4 hi = make_float4(v[4][j], v[5][j], v[6][j], v[7][j]);
            float* p = out + (size_t)c * NN + r0 + ty * 8;
            *(float4*)p       = lo;
            *(float4*)(p + 4) = hi;
        }
    }
}

// ---------------- warp-per-row top-K (no block barriers) ----------------
__global__ void topk_warp(const float* __restrict__ d2, int* __restrict__ idx) {
    __shared__ float sk[8][32 * KNN];
    __shared__ int   si[8][32 * KNN];
    int w = threadIdx.x >> 5, lane = threadIdx.x & 31;
    int row = blockIdx.x * 8 + w;                       // 0 .. BB*NN-1
    const float* r = d2 + (size_t)row * NN;

    float key[KNN]; int ki[KNN];
#pragma unroll
    for (int j = 0; j < KNN; ++j) { key[j] = FLT_MAX; ki[j] = 0; }

    for (int i = lane; i < NN; i += 32) {
        float v = r[i];
        if (v < key[KNN - 1]) {
            float cv = v; int ci = i;
#pragma unroll
            for (int j = 0; j < KNN; ++j) {
                if (cv < key[j]) {
                    float tv = key[j]; key[j] = cv; cv = tv;
                    int ti = ki[j]; ki[j] = ci; ci = ti;
                }
            }
        }
    }
#pragma unroll
    for (int j = 0; j < KNN; ++j) {
        sk[w][lane * KNN + j] = key[j];
        si[w][lane * KNN + j] = ki[j];
    }
    __syncwarp();

    // merge 32 sorted lists: 20 rounds of warp-argmin over head elements
    int h = 0;
    float hv = key[0]; int hi = ki[0];
    for (int k = 0; k < KNN; ++k) {
        unsigned ub = __float_as_uint(hv);
        ub = (ub & 0x80000000u) ? ~ub : (ub | 0x80000000u);
        unsigned long long pk = ((unsigned long long)ub << 32) | (unsigned)lane;
#pragma unroll
        for (int off = 16; off; off >>= 1) {
            unsigned long long o = __shfl_xor_sync(0xffffffffu, pk, off);
            pk = (o < pk) ? o : pk;
        }
        int src = (int)(pk & 31u);
        int widx = __shfl_sync(0xffffffffu, hi, src);
        if (lane == 0) idx[(size_t)row * KNN + k] = widx;
        if (lane == src) {
            ++h;
            hv = (h < KNN) ? sk[w][lane * KNN + h] : FLT_MAX;
            hi = (h < KNN) ? si[w][lane * KNN + h] : 0;
        }
    }
}

// ---------------- SGEMM 128x128x16, 8x8 micro: out[m,o] = sum_k X[m,k]*W[o,woff+k] ----
__global__ void gemm128(const float* __restrict__ X, int ldx,
                        const float* __restrict__ W, int wld, int woff,
                        const float* __restrict__ bias,
                        float* __restrict__ out, int ldo,
                        int Nout, int K, int act) {
    __shared__ float As[16][132];
    __shared__ float Bs[16][132];
    int m0 = blockIdx.y * 128, o0 = blockIdx.x * 128;
    int tx = threadIdx.x & 15, ty = threadIdx.x >> 4;
    float acc[8][8] = {};

    for (int k0 = 0; k0 < K; k0 += 16) {
#pragma unroll
        for (int i = 0; i < 8; ++i) {
            int e = threadIdx.x + 256 * i;
            int m = e >> 4, kk = e & 15;
            int kg = k0 + kk;
            As[kk][m] = (kg < K) ? X[(size_t)(m0 + m) * ldx + kg] : 0.f;
            int o = o0 + m;
            Bs[kk][m] = (kg < K && o < Nout) ? W[(size_t)o * wld + woff + kg] : 0.f;
        }
        __syncthreads();
#pragma unroll
        for (int k = 0; k < 16; ++k) {
            float a[8], bb[8];
            *(float4*)&a[0]  = *(const float4*)&As[k][ty * 8];
            *(float4*)&a[4]  = *(const float4*)&As[k][ty * 8 + 4];
            *(float4*)&bb[0] = *(const float4*)&Bs[k][tx * 8];
            *(float4*)&bb[4] = *(const float4*)&Bs[k][tx * 8 + 4];
#pragma unroll
            for (int i = 0; i < 8; ++i)
#pragma unroll
                for (int j = 0; j < 8; ++j) acc[i][j] += a[i] * bb[j];
        }
        __syncthreads();
    }

#pragma unroll
    for (int i = 0; i < 8; ++i) {
        int m = m0 + ty * 8 + i;
#pragma unroll
        for (int jb = 0; jb < 8; jb += 4) {
            int o = o0 + tx * 8 + jb;
            if (o < Nout) {
                float4 v;
                float* pv = &v.x;
#pragma unroll
                for (int j = 0; j < 4; ++j) {
                    float u = acc[i][jb + j];
                    if (bias) u += bias[o + j];
                    if (act)  u = u > 0.f ? u : 0.2f * u;
                    pv[j] = u;
                }
                *(float4*)(out + (size_t)m * ldo + o) = v;
            }
        }
    }
}

// ---------------- edge epilogue: h[n,o] = max_k leaky(Y[j_k,o] - Y[n,o] + C[n,o]) ----
__global__ void edgemax(const float* __restrict__ y, const float* __restrict__ c,
                        const int* __restrict__ idx, float* __restrict__ out,
                        int O, int ldo) {
    __shared__ int sid[KNN];
    int b = blockIdx.y, n = blockIdx.x;
    int t = threadIdx.x;  // blockDim.x == O
    if (t < KNN) sid[t] = idx[((size_t)b * NN + n) * KNN + t];
    __syncthreads();
    size_t mbase = (size_t)b * NN;
    float yc = y[(mbase + n) * O + t];
    float cc = c[(mbase + n) * O + t];
    float m = -FLT_MAX;
#pragma unroll
    for (int k = 0; k < KNN; ++k) {
        float v = y[(mbase + sid[k]) * O + t] - yc + cc;
        v = v > 0.f ? v : 0.2f * v;
        m = fmaxf(m, v);
    }
    out[(mbase + n) * ldo + t] = m;
}

// ---------------- global max pool over N ----------------
__global__ void maxpool(const float* __restrict__ tmp, float* __restrict__ out) {
    int b = blockIdx.y;
    int f = blockIdx.x * blockDim.x + threadIdx.x;  // 0..1023
    const float* p = tmp + (size_t)b * NN * 1024 + f;
    float m = -FLT_MAX;
    for (int n = 0; n < NN; ++n) m = fmaxf(m, p[(size_t)n * 1024]);
    out[b * 1024 + f] = m;
}

// ---------------- launch ----------------
extern "C" void kernel_launch(void* const* d_in, const int* in_sizes, int n_in,
                              void* d_out, int out_size) {
    const float* x     = (const float*)d_in[0];
    const float* Wl[4] = {(const float*)d_in[1], (const float*)d_in[3],
                          (const float*)d_in[5], (const float*)d_in[7]};
    const float* bl[4] = {(const float*)d_in[2], (const float*)d_in[4],
                          (const float*)d_in[6], (const float*)d_in[8]};
    const float* Wf = (const float*)d_in[9];
    const float* bf = (const float*)d_in[10];
    float* out = (float*)d_out;

    float *p_d2, *p_xx, *p_y, *p_c, *p_hcat, *p_tmp;
    int* p_idx;
    cudaGetSymbolAddress((void**)&p_d2,   g_d2);
    cudaGetSymbolAddress((void**)&p_xx,   g_xx);
    cudaGetSymbolAddress((void**)&p_idx,  g_idx);
    cudaGetSymbolAddress((void**)&p_y,    g_y);
    cudaGetSymbolAddress((void**)&p_c,    g_c);
    cudaGetSymbolAddress((void**)&p_hcat, g_hcat);
    cudaGetSymbolAddress((void**)&p_tmp,  g_tmp);

    const int Cs[4]  = {3, 64, 64, 128};
    const int Os[4]  = {64, 64, 128, 256};
    const int off[4] = {0, 64, 128, 256};
    const int NTILE  = NN / 128;                      // 16
    const int NTRI   = NTILE * (NTILE + 1) / 2;       // 136

    const float* Xin = x;
    int ldx = 3;
    for (int l = 0; l < 4; ++l) {
        int C = Cs[l], O = Os[l];
        xx_kernel<<<(BB * NN + 255) / 256, 256>>>(Xin, ldx, C, p_xx);
        pairwise128<<<dim3(NTRI, BB), 256>>>(Xin, ldx, C, p_xx, p_d2);
        topk_warp<<<(BB * NN) / 8, 256>>>(p_d2, p_idx);
        gemm128<<<dim3((O + 127) / 128, (BB * NN) / 128), 256>>>(
            Xin, ldx, Wl[l], 2 * C, 0, nullptr, p_y, O, O, C, 0);
        gemm128<<<dim3((O + 127) / 128, (BB * NN) / 128), 256>>>(
            Xin, ldx, Wl[l], 2 * C, C, bl[l], p_c, O, O, C, 0);
        edgemax<<<dim3(NN, BB), O>>>(p_y, p_c, p_idx, p_hcat + off[l], O, 512);
        Xin = p_hcat + off[l];
        ldx = 512;
    }
    // final 512 -> 1024 linear + leaky, then max over N
    gemm128<<<dim3(1024 / 128, (BB * NN) / 128), 256>>>(
        p_hcat, 512, Wf, 512, 0, bf, p_tmp, 1024, 1024, 512, 1);
    maxpool<<<dim3(1024 / 256, BB), 256>>>(p_tmp, out);
}

// round 4
// speedup vs baseline: 1.4148x; 1.1837x over previous
#include <cuda_runtime.h>
#include <cuda_bf16.h>
#include <float.h>
#include <math.h>
#include <cstdint>

#define BB  8
#define NN  2048
#define KNN 20

// ---------------- scratch (device globals; no allocations) ----------------
__device__ float g_d2[(size_t)BB * NN * NN];
__device__ float g_xx[BB * NN];
__device__ int   g_idx[BB * NN * KNN];
__device__ float g_y[(size_t)BB * NN * 256];
__device__ float g_c[(size_t)BB * NN * 256];
__device__ float g_hcat[(size_t)BB * NN * 512];
__device__ float g_tmp[(size_t)BB * NN * 1024];
__device__ __nv_bfloat16 g_a3[(size_t)BB * NN * 1536];   // split-bf16 A (h|l|h)
__device__ __nv_bfloat16 g_b3[(size_t)BB * NN * 384];    // split-bf16 B (h|h|l) pairwise
__device__ __nv_bfloat16 g_bf3[1024 * 1536];             // split-bf16 Wf
__device__ __nv_bfloat16 g_w3[256 * 384];                // split-bf16 layer W slice

// =================== split-precision conversion kernels ===================
__global__ void convA_kernel(const float* __restrict__ in, int ld, int C,
                             __nv_bfloat16* __restrict__ out, int K3) {
    int r = blockIdx.y;
    int c = blockIdx.x * 256 + threadIdx.x;
    if (c >= K3) return;
    size_t ro = (size_t)r * K3;
    if (c < C) {
        float xv = in[(size_t)r * ld + c];
        __nv_bfloat16 h = __float2bfloat16(xv);
        __nv_bfloat16 l = __float2bfloat16(xv - __bfloat162float(h));
        out[ro + c] = h; out[ro + C + c] = l; out[ro + 2 * C + c] = h;
    } else if (c >= 3 * C) {
        out[ro + c] = __float2bfloat16(0.f);
    }
}
__global__ void convB_kernel(const float* __restrict__ in, int ld, int C,
                             __nv_bfloat16* __restrict__ out, int K3) {
    int r = blockIdx.y;
    int c = blockIdx.x * 256 + threadIdx.x;
    if (c >= K3) return;
    size_t ro = (size_t)r * K3;
    if (c < C) {
        float xv = in[(size_t)r * ld + c];
        __nv_bfloat16 h = __float2bfloat16(xv);
        __nv_bfloat16 l = __float2bfloat16(xv - __bfloat162float(h));
        out[ro + c] = h; out[ro + C + c] = h; out[ro + 2 * C + c] = l;
    } else if (c >= 3 * C) {
        out[ro + c] = __float2bfloat16(0.f);
    }
}

// =================== mma.sync bf16 GEMM, 128x128 block tile ===================
// out = A3 · B3^T, fp32 accum.  8 warps, 32x64 warp tile, m16n8k16 MMAs.
// mode 0: out[m][o] = (acc + bias[o]) [leaky if act]
// mode 1: out[m][o] = xx[m] - 2*acc + xx[o]
#define LDP 72   // padded k-stride (bf16 elems) -> conflict-free frags

__device__ __forceinline__ void mma16816(float* d, const uint32_t* a, const uint32_t* b) {
    asm volatile(
        "mma.sync.aligned.m16n8k16.row.col.f32.bf16.bf16.f32 "
        "{%0,%1,%2,%3}, {%4,%5,%6,%7}, {%8,%9}, {%0,%1,%2,%3};"
        : "+f"(d[0]), "+f"(d[1]), "+f"(d[2]), "+f"(d[3])
        : "r"(a[0]), "r"(a[1]), "r"(a[2]), "r"(a[3]), "r"(b[0]), "r"(b[1]));
}

__global__ void __launch_bounds__(256)
mma_gemm(const __nv_bfloat16* __restrict__ A3, int lda3, size_t zsA,
         const __nv_bfloat16* __restrict__ B3, int ldb3, size_t zsB,
         int Nvalid, int K3,
         float* __restrict__ out, int ldo, size_t zsO,
         const float* __restrict__ bias, int act,
         int mode, const float* __restrict__ xx, int zsXX) {
    __shared__ __nv_bfloat16 As[128][LDP];
    __shared__ __nv_bfloat16 Bs[128][LDP];

    int tid = threadIdx.x;
    int wid = tid >> 5, lane = tid & 31;
    int wr = wid & 3, wc = wid >> 2;         // 4 x 2 warp grid
    int gr = lane >> 2, tg = lane & 3;

    int m0 = blockIdx.y * 128, o0 = blockIdx.x * 128;
    const __nv_bfloat16* Ab = A3 + blockIdx.z * zsA;
    const __nv_bfloat16* Bb = B3 + blockIdx.z * zsB;

    float acc[2][8][4] = {};

    for (int k0 = 0; k0 < K3; k0 += 64) {
        // load A,B 128x64 tiles (uint4 = 8 bf16); 4 vectors each per thread
#pragma unroll
        for (int i = 0; i < 4; ++i) {
            int e = tid + i * 256;           // 0..1023
            int row = e >> 3, seg = e & 7;
            uint4 va = *((const uint4*)(Ab + (size_t)(m0 + row) * lda3 + k0) + seg);
            *(uint4*)&As[row][seg * 8] = va;
            int brow = o0 + row;
            uint4 vb = make_uint4(0, 0, 0, 0);
            if (brow < Nvalid)
                vb = *((const uint4*)(Bb + (size_t)brow * ldb3 + k0) + seg);
            *(uint4*)&Bs[row][seg * 8] = vb;
        }
        __syncthreads();

#pragma unroll
        for (int kk = 0; kk < 64; kk += 16) {
            uint32_t af[2][4], bfr[8][2];
#pragma unroll
            for (int mi = 0; mi < 2; ++mi) {
                const __nv_bfloat16* pa = &As[wr * 32 + mi * 16 + gr][kk + tg * 2];
                af[mi][0] = *(const uint32_t*)pa;
                af[mi][1] = *(const uint32_t*)(pa + 8 * LDP);
                af[mi][2] = *(const uint32_t*)(pa + 8);
                af[mi][3] = *(const uint32_t*)(pa + 8 * LDP + 8);
            }
#pragma unroll
            for (int ni = 0; ni < 8; ++ni) {
                const __nv_bfloat16* pb = &Bs[wc * 64 + ni * 8 + gr][kk + tg * 2];
                bfr[ni][0] = *(const uint32_t*)pb;
                bfr[ni][1] = *(const uint32_t*)(pb + 8);
            }
#pragma unroll
            for (int mi = 0; mi < 2; ++mi)
#pragma unroll
                for (int ni = 0; ni < 8; ++ni)
                    mma16816(acc[mi][ni], af[mi], bfr[ni]);
        }
        __syncthreads();
    }

    // -------- epilogue (register fragments -> gmem) --------
    float* outb = out + blockIdx.z * zsO;
    const float* xxb = (mode == 1) ? xx + (size_t)blockIdx.z * zsXX : nullptr;
#pragma unroll
    for (int mi = 0; mi < 2; ++mi) {
        int mA = m0 + wr * 32 + mi * 16 + gr;
        float xrA = 0.f, xrB = 0.f;
        if (mode == 1) { xrA = xxb[mA]; xrB = xxb[mA + 8]; }
#pragma unroll
        for (int ni = 0; ni < 8; ++ni) {
            int o = o0 + wc * 64 + ni * 8 + tg * 2;
            if (o < Nvalid) {
                float u0 = acc[mi][ni][0], u1 = acc[mi][ni][1];
                float u2 = acc[mi][ni][2], u3 = acc[mi][ni][3];
                if (mode == 0) {
                    float b0 = bias ? bias[o] : 0.f, b1 = bias ? bias[o + 1] : 0.f;
                    u0 += b0; u1 += b1; u2 += b0; u3 += b1;
                    if (act) {
                        u0 = u0 > 0.f ? u0 : 0.2f * u0;
                        u1 = u1 > 0.f ? u1 : 0.2f * u1;
                        u2 = u2 > 0.f ? u2 : 0.2f * u2;
                        u3 = u3 > 0.f ? u3 : 0.2f * u3;
                    }
                } else {
                    float xc0 = xxb[o], xc1 = xxb[o + 1];
                    u0 = xrA - 2.f * u0 + xc0; u1 = xrA - 2.f * u1 + xc1;
                    u2 = xrB - 2.f * u2 + xc0; u3 = xrB - 2.f * u3 + xc1;
                }
                *(float2*)(outb + (size_t)mA * ldo + o)       = make_float2(u0, u1);
                *(float2*)(outb + (size_t)(mA + 8) * ldo + o) = make_float2(u2, u3);
            }
        }
    }
}

// =================== small kernels ===================
__global__ void xx_kernel(const float* __restrict__ X, int ldx, int C,
                          float* __restrict__ xx) {
    int i = blockIdx.x * blockDim.x + threadIdx.x;
    if (i >= BB * NN) return;
    const float* p = X + (size_t)i * ldx;
    float s = 0.f;
    for (int c = 0; c < C; ++c) { float v = p[c]; s += v * v; }
    xx[i] = s;
}

__global__ void topk_warp(const float* __restrict__ d2, int* __restrict__ idx) {
    __shared__ float sk[8][32 * KNN];
    __shared__ int   si[8][32 * KNN];
    int w = threadIdx.x >> 5, lane = threadIdx.x & 31;
    int row = blockIdx.x * 8 + w;
    const float* r = d2 + (size_t)row * NN;
    float key[KNN]; int ki[KNN];
#pragma unroll
    for (int j = 0; j < KNN; ++j) { key[j] = FLT_MAX; ki[j] = 0; }
    for (int i = lane; i < NN; i += 32) {
        float v = r[i];
        if (v < key[KNN - 1]) {
            float cv = v; int ci = i;
#pragma unroll
            for (int j = 0; j < KNN; ++j) {
                if (cv < key[j]) {
                    float tv = key[j]; key[j] = cv; cv = tv;
                    int ti = ki[j]; ki[j] = ci; ci = ti;
                }
            }
        }
    }
#pragma unroll
    for (int j = 0; j < KNN; ++j) {
        sk[w][lane * KNN + j] = key[j];
        si[w][lane * KNN + j] = ki[j];
    }
    __syncwarp();
    int h = 0;
    float hv = key[0]; int hi = ki[0];
    for (int k = 0; k < KNN; ++k) {
        unsigned ub = __float_as_uint(hv);
        ub = (ub & 0x80000000u) ? ~ub : (ub | 0x80000000u);
        unsigned long long pk = ((unsigned long long)ub << 32) | (unsigned)lane;
#pragma unroll
        for (int off = 16; off; off >>= 1) {
            unsigned long long o = __shfl_xor_sync(0xffffffffu, pk, off);
            pk = (o < pk) ? o : pk;
        }
        int src = (int)(pk & 31u);
        int widx = __shfl_sync(0xffffffffu, hi, src);
        if (lane == 0) idx[(size_t)row * KNN + k] = widx;
        if (lane == src) {
            ++h;
            hv = (h < KNN) ? sk[w][lane * KNN + h] : FLT_MAX;
            hi = (h < KNN) ? si[w][lane * KNN + h] : 0;
        }
    }
}

__global__ void edgemax(const float* __restrict__ y, const float* __restrict__ c,
                        const int* __restrict__ idx, float* __restrict__ out,
                        int O, int ldo) {
    __shared__ int sid[KNN];
    int b = blockIdx.y, n = blockIdx.x;
    int t = threadIdx.x;
    if (t < KNN) sid[t] = idx[((size_t)b * NN + n) * KNN + t];
    __syncthreads();
    size_t mbase = (size_t)b * NN;
    float yc = y[(mbase + n) * O + t];
    float cc = c[(mbase + n) * O + t];
    float m = -FLT_MAX;
#pragma unroll
    for (int k = 0; k < KNN; ++k) {
        float v = y[(mbase + sid[k]) * O + t] - yc + cc;
        v = v > 0.f ? v : 0.2f * v;
        m = fmaxf(m, v);
    }
    out[(mbase + n) * ldo + t] = m;
}

__global__ void maxpool(const float* __restrict__ tmp, float* __restrict__ out) {
    int b = blockIdx.y;
    int f = blockIdx.x * blockDim.x + threadIdx.x;
    const float* p = tmp + (size_t)b * NN * 1024 + f;
    float m = -FLT_MAX;
    for (int n = 0; n < NN; ++n) m = fmaxf(m, p[(size_t)n * 1024]);
    out[b * 1024 + f] = m;
}

// =================== launch ===================
extern "C" void kernel_launch(void* const* d_in, const int* in_sizes, int n_in,
                              void* d_out, int out_size) {
    const float* x     = (const float*)d_in[0];
    const float* Wl[4] = {(const float*)d_in[1], (const float*)d_in[3],
                          (const float*)d_in[5], (const float*)d_in[7]};
    const float* bl[4] = {(const float*)d_in[2], (const float*)d_in[4],
                          (const float*)d_in[6], (const float*)d_in[8]};
    const float* Wf = (const float*)d_in[9];
    const float* bf = (const float*)d_in[10];
    float* out = (float*)d_out;

    float *p_d2, *p_xx, *p_y, *p_c, *p_hcat, *p_tmp;
    __nv_bfloat16 *p_a3, *p_b3, *p_bf3, *p_w3;
    int* p_idx;
    cudaGetSymbolAddress((void**)&p_d2,   g_d2);
    cudaGetSymbolAddress((void**)&p_xx,   g_xx);
    cudaGetSymbolAddress((void**)&p_idx,  g_idx);
    cudaGetSymbolAddress((void**)&p_y,    g_y);
    cudaGetSymbolAddress((void**)&p_c,    g_c);
    cudaGetSymbolAddress((void**)&p_hcat, g_hcat);
    cudaGetSymbolAddress((void**)&p_tmp,  g_tmp);
    cudaGetSymbolAddress((void**)&p_a3,   g_a3);
    cudaGetSymbolAddress((void**)&p_b3,   g_b3);
    cudaGetSymbolAddress((void**)&p_bf3,  g_bf3);
    cudaGetSymbolAddress((void**)&p_w3,   g_w3);

    const int Cs[4]  = {3, 64, 64, 128};
    const int Os[4]  = {64, 64, 128, 256};
    const int off[4] = {0, 64, 128, 256};

    const float* Xin = x;
    int ldx = 3;
    for (int l = 0; l < 4; ++l) {
        int C = Cs[l], O = Os[l];
        int K3 = ((3 * C + 63) / 64) * 64;     // 64, 192, 192, 384

        xx_kernel<<<(BB * NN + 255) / 256, 256>>>(Xin, ldx, C, p_xx);
        convA_kernel<<<dim3((K3 + 255) / 256, BB * NN), 256>>>(Xin, ldx, C, p_a3, K3);
        convB_kernel<<<dim3((K3 + 255) / 256, BB * NN), 256>>>(Xin, ldx, C, p_b3, K3);
        // pairwise d2 (batched over z)
        mma_gemm<<<dim3(16, 16, BB), 256>>>(
            p_a3, K3, (size_t)NN * K3, p_b3, K3, (size_t)NN * K3,
            NN, K3, p_d2, NN, (size_t)NN * NN, nullptr, 0, 1, p_xx, NN);
        topk_warp<<<(BB * NN) / 8, 256>>>(p_d2, p_idx);
        // y = X * Wy^T
        convB_kernel<<<dim3((K3 + 255) / 256, O), 256>>>(Wl[l], 2 * C, C, p_w3, K3);
        mma_gemm<<<dim3((O + 127) / 128, (BB * NN) / 128, 1), 256>>>(
            p_a3, K3, 0, p_w3, K3, 0, O, K3,
            p_y, O, 0, nullptr, 0, 0, nullptr, 0);
        // c = X * Wc^T + b
        convB_kernel<<<dim3((K3 + 255) / 256, O), 256>>>(Wl[l] + C, 2 * C, C, p_w3, K3);
        mma_gemm<<<dim3((O + 127) / 128, (BB * NN) / 128, 1), 256>>>(
            p_a3, K3, 0, p_w3, K3, 0, O, K3,
            p_c, O, 0, bl[l], 0, 0, nullptr, 0);
        edgemax<<<dim3(NN, BB), O>>>(p_y, p_c, p_idx, p_hcat + off[l], O, 512);
        Xin = p_hcat + off[l];
        ldx = 512;
    }
    // final 512 -> 1024 linear + leaky, then max over N
    convA_kernel<<<dim3(1536 / 256, BB * NN), 256>>>(p_hcat, 512, 512, p_a3, 1536);
    convB_kernel<<<dim3(1536 / 256, 1024), 256>>>(Wf, 512, 512, p_bf3, 1536);
    mma_gemm<<<dim3(1024 / 128, (BB * NN) / 128, 1), 256>>>(
        p_a3, 1536, 0, p_bf3, 1536, 0, 1024, 1536,
        p_tmp, 1024, 0, bf, 1, 0, nullptr, 0);
    maxpool<<<dim3(1024 / 256, BB), 256>>>(p_tmp, out);
}